// round 8
// baseline (speedup 1.0000x reference)
#include <cuda_runtime.h>
#include <cstdint>

typedef uint32_t u32;

#define N_TOK 1024
#define TZ 128
#define TD 64
#define NB 38
#define EPSF 1e-5f
#define TM 128
#define THREADS 512
#define NBLOCKS 152
#define NTILES ((N_TOK * N_TOK) / TM)   // 8192

// smem strides (floats) — chosen for conflict-free fragment loads
#define ZSTR 132     // 132 % 32 == 4
#define VSTR 68      // 68 % 32 == 4
#define W1STR 72     // 72 % 32 == 8
#define W2STR 136    // 136 % 32 == 8

// smem float offsets
#define ZA0_F 0                       // z buf0 128x132
#define ZA1_F (TM * ZSTR)             // z buf1
#define W1_F  (2 * TM * ZSTR)         // W1'[k][n] 128x72
#define W2_F  (W1_F + TZ * W1STR)     // W2 [d][c] 64x136
#define WAS_F (W2_F + TD * W2STR)     // Wa [bin][d] 38x64
#define S_F   (WAS_F + NB * TD)
#define T_F   (S_F + TD)
#define VG_F  (T_F + TD)
#define VB_F  (VG_F + TD)
#define LN2_F (VB_F + TD)             // 8 floats per row: (s,q) x 4 col-groups
#define SMEM_FLOATS (LN2_F + 8 * TM)

// ---------------- helpers ----------------
__device__ __forceinline__ float rna_tf32(float x) {
    u32 r;
    asm("cvt.rna.tf32.f32 %0, %1;" : "=r"(r) : "f"(x));
    return __uint_as_float(r);
}
__device__ __forceinline__ u32 rna_tf32u(float x) {
    u32 r;
    asm("cvt.rna.tf32.f32 %0, %1;" : "=r"(r) : "f"(x));
    return r;
}
__device__ __forceinline__ void cpa16(float* dst, const void* g) {
    u32 a = (u32)__cvta_generic_to_shared(dst);
    asm volatile("cp.async.cg.shared.global [%0], [%1], 16;" :: "r"(a), "l"(g));
}
__device__ __forceinline__ void cpa_commit() { asm volatile("cp.async.commit_group;"); }
__device__ __forceinline__ void cpa_wait0() { asm volatile("cp.async.wait_group 0;" ::: "memory"); }

// D += A(16x8,row) * B(8x8,col), tf32
__device__ __forceinline__ void mma8(float* c, const u32* a, u32 b0, u32 b1) {
    asm volatile(
        "mma.sync.aligned.m16n8k8.row.col.f32.tf32.tf32.f32 "
        "{%0,%1,%2,%3}, {%4,%5,%6,%7}, {%8,%9}, {%0,%1,%2,%3};"
        : "+f"(c[0]), "+f"(c[1]), "+f"(c[2]), "+f"(c[3])
        : "r"(a[0]), "r"(a[1]), "r"(a[2]), "r"(a[3]), "r"(b0), "r"(b1));
}
__device__ __forceinline__ u32 ldsf(const float* p) { return __float_as_uint(*p); }

// ---------------- main fused kernel ----------------
__global__ __launch_bounds__(THREADS, 1)
void td_kernel(const float* __restrict__ z, const float* __restrict__ cc,
               const float* __restrict__ tdm, const float* __restrict__ Wz,
               const float* __restrict__ Wa, const float* __restrict__ Wu,
               const float* __restrict__ zg, const float* __restrict__ zb,
               const float* __restrict__ vg, const float* __restrict__ vb,
               float* __restrict__ out)
{
    extern __shared__ float smf[];
    const int t = threadIdx.x;
    const int wid = t >> 5, lane = t & 31;
    const int g = lane >> 2, tg = lane & 3;

    // ---- prefetch first tile (overlaps weight staging) ----
    const int tile0 = blockIdx.x;
    {
        const float* src = z + (size_t)tile0 * TM * TZ;
        #pragma unroll
        for (int i = 0; i < 8; i++) {
            int e = i * THREADS + t;            // 0..4095 float4
            cpa16(&smf[ZA0_F + (e >> 5) * ZSTR + (e & 31) * 4], src + e * 4);
        }
        cpa_commit();
    }

    // ---- one-time weight staging ----
    for (int s = t; s < TZ * TD; s += THREADS) {        // W1'[k][n] = Wz[n][k]*zg[k]
        int k = s >> 6, n = s & 63;
        smf[W1_F + k * W1STR + n] = rna_tf32(Wz[n * TZ + k] * zg[k]);
    }
    for (int s = t; s < TD * TZ; s += THREADS) {        // W2[d][c] = Wu[c][d]
        int d = s >> 7, c = s & 127;
        smf[W2_F + d * W2STR + c] = rna_tf32(Wu[c * TD + d]);
    }
    for (int s = t; s < NB * TD; s += THREADS) {        // Was[bin][d]
        int k = s >> 6, d = s & 63;
        smf[WAS_F + k * TD + d] = Wa[d * NB + k];
    }
    if (t < TD) {
        float S = 0.f, T = 0.f;
        for (int k = 0; k < TZ; k++) {
            S += rna_tf32(Wz[t * TZ + k] * zg[k]);
            T += Wz[t * TZ + k] * zb[k];
        }
        smf[S_F + t] = S; smf[T_F + t] = T;
        smf[VG_F + t] = vg[t]; smf[VB_F + t] = vb[t];
    }

    const int rb = wid & 3, cg = wid >> 2;     // warp grid 4 rows x 4 cols
    const int R1 = rb * 32;
    const int C1 = cg * 16;                    // GEMM1 cols (16 per warp)
    const int C2 = cg * 32;                    // GEMM2 cols (32 per warp)

    int cur = 0;
    for (int tile = tile0; tile < NTILES; tile += NBLOCKS) {
        const int base_p = tile * TM;
        const int nt_idx = tile + NBLOCKS;
        float* zc = &smf[cur ? ZA1_F : ZA0_F];
        float* zn = &smf[cur ? ZA0_F : ZA1_F];

        cpa_wait0();
        __syncthreads();   // zc ready; all warps past last tile's GEMM2 (zn free)

        // prefetch next tile (overlapped with GEMM1/epilogues)
        if (nt_idx < NTILES) {
            const float* src = z + (size_t)nt_idx * TM * TZ;
            #pragma unroll
            for (int i = 0; i < 8; i++) {
                int e = i * THREADS + t;
                cpa16(&zn[(e >> 5) * ZSTR + (e & 31) * 4], src + e * 4);
            }
            cpa_commit();
        }

        // ---- per-thread distance bin + mask for this thread's 4 output rows ----
        int binreg[4];
        float mkreg[4];
        {
            const int i0 = base_p >> 10;
            const int jb = base_p & (N_TOK - 1);
            const float cx = __ldg(cc + i0 * 3 + 0);
            const float cy = __ldg(cc + i0 * 3 + 1);
            const float cz = __ldg(cc + i0 * 3 + 2);
            #pragma unroll
            for (int i = 0; i < 4; i++) {
                const int row = R1 + g + 8 * i;
                const int j0 = jb + row;
                float dx = cx - __ldg(cc + j0 * 3 + 0);
                float dy = cy - __ldg(cc + j0 * 3 + 1);
                float dz = cz - __ldg(cc + j0 * 3 + 2);
                float dist = sqrtf(dx * dx + dy * dy + dz * dz);
                int idx = 0;
                #pragma unroll
                for (int k = 0; k < NB - 1; k++) {
                    float b = (float)(3.25 + k * (47.5 / 36.0));
                    idx += (dist > b) ? 1 : 0;
                }
                binreg[i] = idx;
                mkreg[i] = __ldg(tdm + base_p + row);
            }
        }

        // ---- GEMM1 + fused LN1 stats: warp tile 32x16 ----
        float acc[2][2][4];
        #pragma unroll
        for (int a = 0; a < 2; a++)
            #pragma unroll
            for (int b = 0; b < 2; b++)
                #pragma unroll
                for (int cI = 0; cI < 4; cI++) acc[a][b][cI] = 0.f;

        float sst[4] = {0.f, 0.f, 0.f, 0.f};
        float sqt[4] = {0.f, 0.f, 0.f, 0.f};

        #pragma unroll 4
        for (int ks = 0; ks < 16; ks++) {
            const int k0 = ks * 8;
            u32 afr[2][4];
            #pragma unroll
            for (int rt = 0; rt < 2; rt++) {
                const float* zr = &zc[(R1 + 16 * rt + g) * ZSTR + k0 + tg];
                float v0 = zr[0];
                float v1 = zr[8 * ZSTR];
                float v2 = zr[4];
                float v3 = zr[8 * ZSTR + 4];
                sst[2 * rt + 0] += v0 + v2;
                sqt[2 * rt + 0] += v0 * v0 + v2 * v2;
                sst[2 * rt + 1] += v1 + v3;
                sqt[2 * rt + 1] += v1 * v1 + v3 * v3;
                afr[rt][0] = rna_tf32u(v0);
                afr[rt][1] = rna_tf32u(v1);
                afr[rt][2] = rna_tf32u(v2);
                afr[rt][3] = rna_tf32u(v3);
            }
            #pragma unroll
            for (int nt = 0; nt < 2; nt++) {
                const float* wr = &smf[W1_F + (k0 + tg) * W1STR + C1 + 8 * nt + g];
                u32 b0 = ldsf(wr);
                u32 b1 = ldsf(wr + 4 * W1STR);
                mma8(acc[0][nt], afr[0], b0, b1);
                mma8(acc[1][nt], afr[1], b0, b1);
            }
        }

        // finalize LN1 stats per row-slot
        float m1r[4], rs1r[4];
        #pragma unroll
        for (int i = 0; i < 4; i++) {
            float s = sst[i], q = sqt[i];
            s += __shfl_xor_sync(0xffffffffu, s, 1);
            q += __shfl_xor_sync(0xffffffffu, q, 1);
            s += __shfl_xor_sync(0xffffffffu, s, 2);
            q += __shfl_xor_sync(0xffffffffu, q, 2);
            float m = s * (1.f / TZ);
            float var = fmaxf(q * (1.f / TZ) - m * m, 0.f);
            m1r[i] = m;
            rs1r[i] = rsqrtf(var + EPSF);
        }

        // ---- epilogue 1: LN1-fold + bin column + LN2 partials ----
        #pragma unroll
        for (int i = 0; i < 4; i++) {
            const int row = R1 + g + 8 * i;
            const int rt = i >> 1, cp = (i & 1) * 2;
            const float m1 = m1r[i], r1 = rs1r[i], mk = mkreg[i];
            const int bin = binreg[i];
            float s2 = 0.f, q2 = 0.f;
            #pragma unroll
            for (int nt = 0; nt < 2; nt++) {
                const int col = C1 + 8 * nt + 2 * tg;
                float2 Sv = *(const float2*)&smf[S_F + col];
                float2 Tv = *(const float2*)&smf[T_F + col];
                float2 Wv = *(const float2*)&smf[WAS_F + bin * TD + col];
                float v0 = r1 * (acc[rt][nt][cp]     - m1 * Sv.x) + Tv.x + mk * Wv.x;
                float v1 = r1 * (acc[rt][nt][cp + 1] - m1 * Sv.y) + Tv.y + mk * Wv.y;
                acc[rt][nt][cp] = v0; acc[rt][nt][cp + 1] = v1;
                s2 += v0 + v1;
                q2 += v0 * v0 + v1 * v1;
            }
            s2 += __shfl_xor_sync(0xffffffffu, s2, 1);
            q2 += __shfl_xor_sync(0xffffffffu, q2, 1);
            s2 += __shfl_xor_sync(0xffffffffu, s2, 2);
            q2 += __shfl_xor_sync(0xffffffffu, q2, 2);
            if (tg == 0)
                *(float2*)&smf[LN2_F + row * 8 + cg * 2] = make_float2(s2, q2);
        }
        __syncthreads();

        // ---- LN2 finalize + relu + tf32 -> vn (aliases zc) ----
        float* vn = zc;
        #pragma unroll
        for (int i = 0; i < 4; i++) {
            const int row = R1 + g + 8 * i;
            const int rt = i >> 1, cp = (i & 1) * 2;
            float4 o0 = *(const float4*)&smf[LN2_F + row * 8];
            float4 o1 = *(const float4*)&smf[LN2_F + row * 8 + 4];
            float st = o0.x + o0.z + o1.x + o1.z;
            float qt = o0.y + o0.w + o1.y + o1.w;
            float m2 = st * (1.f / TD);
            float var = fmaxf(qt * (1.f / TD) - m2 * m2, 0.f);
            float sc = 2.f * rsqrtf(4.f * var + EPSF);    // exact v+v doubling
            #pragma unroll
            for (int nt = 0; nt < 2; nt++) {
                const int col = C1 + 8 * nt + 2 * tg;
                float2 gv = *(const float2*)&smf[VG_F + col];
                float2 bv = *(const float2*)&smf[VB_F + col];
                float2 r;
                r.x = rna_tf32(fmaxf(fmaf((acc[rt][nt][cp]     - m2) * sc, gv.x, bv.x), 0.f));
                r.y = rna_tf32(fmaxf(fmaf((acc[rt][nt][cp + 1] - m2) * sc, gv.y, bv.y), 0.f));
                *(float2*)&vn[row * VSTR + col] = r;
            }
        }
        __syncthreads();

        // ---- GEMM2: warp tile 32x32 + direct STG ----
        float acc2[2][4][4];
        #pragma unroll
        for (int a = 0; a < 2; a++)
            #pragma unroll
            for (int b = 0; b < 4; b++)
                #pragma unroll
                for (int cI = 0; cI < 4; cI++) acc2[a][b][cI] = 0.f;

        #pragma unroll 4
        for (int ks = 0; ks < 8; ks++) {
            const int k0 = ks * 8;
            u32 afr[2][4];
            #pragma unroll
            for (int rt = 0; rt < 2; rt++) {
                const float* vr = &vn[(R1 + 16 * rt + g) * VSTR + k0 + tg];
                afr[rt][0] = ldsf(vr);
                afr[rt][2] = ldsf(vr + 4);
                afr[rt][1] = ldsf(vr + 8 * VSTR);
                afr[rt][3] = ldsf(vr + 8 * VSTR + 4);
            }
            #pragma unroll
            for (int nt = 0; nt < 4; nt++) {
                const float* wr = &smf[W2_F + (k0 + tg) * W2STR + C2 + 8 * nt + g];
                u32 b0 = ldsf(wr);
                u32 b1 = ldsf(wr + 4 * W2STR);
                mma8(acc2[0][nt], afr[0], b0, b1);
                mma8(acc2[1][nt], afr[1], b0, b1);
            }
        }
        // epilogue 2: STG.64 per C-pair
        #pragma unroll
        for (int rt = 0; rt < 2; rt++) {
            const int ra = base_p + R1 + 16 * rt + g;
            #pragma unroll
            for (int nt = 0; nt < 4; nt++) {
                const int col = C2 + 8 * nt + 2 * tg;
                *(float2*)&out[(size_t)ra * TZ + col] =
                    make_float2(acc2[rt][nt][0], acc2[rt][nt][1]);
                *(float2*)&out[(size_t)(ra + 8) * TZ + col] =
                    make_float2(acc2[rt][nt][2], acc2[rt][nt][3]);
            }
        }
        cur ^= 1;
    }
}

// ---------------- launch ----------------
extern "C" void kernel_launch(void* const* d_in, const int* in_sizes, int n_in,
                              void* d_out, int out_size) {
    const float* z   = (const float*)d_in[0];   // (1,1024,1024,128)
    const float* cc  = (const float*)d_in[1];   // (1,1024,3)
    const float* tdm = (const float*)d_in[2];   // (1,1024,1024)
    // d_in[3] = pair_mask (unused by reference)
    const float* Wz  = (const float*)d_in[4];   // (64,128)
    const float* Wa  = (const float*)d_in[5];   // (64,38)
    const float* Wu  = (const float*)d_in[6];   // (128,64)
    const float* zg  = (const float*)d_in[7];   // (128)
    const float* zb  = (const float*)d_in[8];   // (128)
    const float* vg  = (const float*)d_in[9];   // (64)
    const float* vb  = (const float*)d_in[10];  // (64)
    float* out = (float*)d_out;

    size_t smem_bytes = (size_t)SMEM_FLOATS * sizeof(float);
    cudaFuncSetAttribute(td_kernel, cudaFuncAttributeMaxDynamicSharedMemorySize, (int)smem_bytes);
    td_kernel<<<NBLOCKS, THREADS, smem_bytes>>>(z, cc, tdm, Wz, Wa, Wu, zg, zb, vg, vb, out);
}

// round 10
// speedup vs baseline: 1.3617x; 1.3617x over previous
#include <cuda_runtime.h>
#include <cstdint>

typedef uint32_t u32;

#define N_TOK 1024
#define TZ 128
#define TD 64
#define NB 38
#define EPSF 1e-5f
#define TM 128
#define THREADS 256
#define NBLOCKS 152
#define NTILES ((N_TOK * N_TOK) / TM)   // 8192

// smem strides (floats) — conflict-free fragment access
#define ZSTR 132     // ≡4 mod 32; ALSO the vn stride (row-aligned aliasing => warp-private)
#define W1STR 72     // ≡8 mod 32
#define W2STR 136    // ≡8 mod 32

// smem float offsets
#define ZA0_F 0                       // z buf0 128x132
#define ZA1_F (TM * ZSTR)             // z buf1
#define W1_F  (2 * TM * ZSTR)         // W1'[k][n] 128x72
#define W2_F  (W1_F + TZ * W1STR)     // W2 [d][c] 64x136
#define WAS_F (W2_F + TD * W2STR)     // Wa [bin][d] 38x64
#define S_F   (WAS_F + NB * TD)
#define T_F   (S_F + TD)
#define VG_F  (T_F + TD)
#define VB_F  (VG_F + TD)
#define SMEM_FLOATS (VB_F + TD)

// ---------------- helpers ----------------
__device__ __forceinline__ float rna_tf32(float x) {
    u32 r;
    asm("cvt.rna.tf32.f32 %0, %1;" : "=r"(r) : "f"(x));
    return __uint_as_float(r);
}
__device__ __forceinline__ u32 rna_tf32u(float x) {
    u32 r;
    asm("cvt.rna.tf32.f32 %0, %1;" : "=r"(r) : "f"(x));
    return r;
}
__device__ __forceinline__ void cpa16(float* dst, const void* g) {
    u32 a = (u32)__cvta_generic_to_shared(dst);
    asm volatile("cp.async.cg.shared.global [%0], [%1], 16;" :: "r"(a), "l"(g));
}
__device__ __forceinline__ void cpa_commit() { asm volatile("cp.async.commit_group;"); }
__device__ __forceinline__ void cpa_wait0() { asm volatile("cp.async.wait_group 0;" ::: "memory"); }

// D += A(16x8,row) * B(8x8,col), tf32
__device__ __forceinline__ void mma8(float* c, const u32* a, u32 b0, u32 b1) {
    asm volatile(
        "mma.sync.aligned.m16n8k8.row.col.f32.tf32.tf32.f32 "
        "{%0,%1,%2,%3}, {%4,%5,%6,%7}, {%8,%9}, {%0,%1,%2,%3};"
        : "+f"(c[0]), "+f"(c[1]), "+f"(c[2]), "+f"(c[3])
        : "r"(a[0]), "r"(a[1]), "r"(a[2]), "r"(a[3]), "r"(b0), "r"(b1));
}
__device__ __forceinline__ u32 ldsf(const float* p) { return __float_as_uint(*p); }

// ---------------- main fused kernel ----------------
__global__ __launch_bounds__(THREADS, 1)
void td_kernel(const float* __restrict__ z, const float* __restrict__ cc,
               const float* __restrict__ tdm, const float* __restrict__ Wz,
               const float* __restrict__ Wa, const float* __restrict__ Wu,
               const float* __restrict__ zg, const float* __restrict__ zb,
               const float* __restrict__ vg, const float* __restrict__ vb,
               float* __restrict__ out)
{
    extern __shared__ float smf[];
    const int t = threadIdx.x;
    const int wid = t >> 5, lane = t & 31;
    const int g = lane >> 2, tg = lane & 3;

    // ---- prefetch first tile (overlaps weight staging) ----
    const int tile0 = blockIdx.x;
    {
        const float* src = z + (size_t)tile0 * TM * TZ;
        #pragma unroll
        for (int i = 0; i < 16; i++) {
            int e = i * THREADS + t;            // 0..4095 float4
            cpa16(&smf[ZA0_F + (e >> 5) * ZSTR + (e & 31) * 4], src + e * 4);
        }
        cpa_commit();
    }

    // ---- one-time weight staging ----
    for (int s = t; s < TZ * TD; s += THREADS) {        // W1'[k][n] = Wz[n][k]*zg[k]
        int k = s >> 6, n = s & 63;
        smf[W1_F + k * W1STR + n] = rna_tf32(Wz[n * TZ + k] * zg[k]);
    }
    for (int s = t; s < TD * TZ; s += THREADS) {        // W2[d][c] = Wu[c][d]
        int d = s >> 7, c = s & 127;
        smf[W2_F + d * W2STR + c] = rna_tf32(Wu[c * TD + d]);
    }
    for (int s = t; s < NB * TD; s += THREADS) {        // Was[bin][d]
        int k = s >> 6, d = s & 63;
        smf[WAS_F + k * TD + d] = Wa[d * NB + k];
    }
    if (t < TD) {
        float S = 0.f, T = 0.f;
        for (int k = 0; k < TZ; k++) {
            S += rna_tf32(Wz[t * TZ + k] * zg[k]);
            T += Wz[t * TZ + k] * zb[k];
        }
        smf[S_F + t] = S; smf[T_F + t] = T;
        smf[VG_F + t] = vg[t]; smf[VB_F + t] = vb[t];
    }

    const int R1 = wid * 16;        // 16 rows per warp, fully warp-private pipeline

    int cur = 0;
    for (int tile = tile0; tile < NTILES; tile += NBLOCKS) {
        const int base_p = tile * TM;
        const int nt_idx = tile + NBLOCKS;
        float* zc = &smf[cur ? ZA1_F : ZA0_F];
        float* zn = &smf[cur ? ZA0_F : ZA1_F];

        cpa_wait0();
        __syncthreads();   // ONLY block barrier per tile: zc ready, zn free

        // prefetch next tile (overlapped with everything below)
        if (nt_idx < NTILES) {
            const float* src = z + (size_t)nt_idx * TM * TZ;
            #pragma unroll
            for (int i = 0; i < 16; i++) {
                int e = i * THREADS + t;
                cpa16(&zn[(e >> 5) * ZSTR + (e & 31) * 4], src + e * 4);
            }
            cpa_commit();
        }

        // ---- per-thread distance bin + mask (rows R1+g, R1+g+8) ----
        int bin0, bin1;
        float mk0, mk1;
        {
            const int i0 = base_p >> 10;
            const int jb = base_p & (N_TOK - 1);
            const float cx = __ldg(cc + i0 * 3 + 0);
            const float cy = __ldg(cc + i0 * 3 + 1);
            const float cz = __ldg(cc + i0 * 3 + 2);
            #pragma unroll
            for (int i = 0; i < 2; i++) {
                const int row = R1 + g + 8 * i;
                const int j0 = jb + row;
                float dx = cx - __ldg(cc + j0 * 3 + 0);
                float dy = cy - __ldg(cc + j0 * 3 + 1);
                float dz = cz - __ldg(cc + j0 * 3 + 2);
                float dist = sqrtf(dx * dx + dy * dy + dz * dz);
                int idx = 0;
                #pragma unroll
                for (int k = 0; k < NB - 1; k++) {
                    float b = (float)(3.25 + k * (47.5 / 36.0));
                    idx += (dist > b) ? 1 : 0;
                }
                if (i == 0) { bin0 = idx; mk0 = __ldg(tdm + base_p + row); }
                else        { bin1 = idx; mk1 = __ldg(tdm + base_p + row); }
            }
        }

        // ---- GEMM1 (warp tile 16x64) + fused LN1 stats ----
        float acc[8][4];
        #pragma unroll
        for (int b = 0; b < 8; b++)
            #pragma unroll
            for (int cI = 0; cI < 4; cI++) acc[b][cI] = 0.f;

        float s0 = 0.f, q0 = 0.f, s1 = 0.f, q1 = 0.f;   // raw stats rows g / g+8

        #pragma unroll 4
        for (int ks = 0; ks < 16; ks++) {
            const int k0 = ks * 8;
            const float* zr = &zc[(R1 + g) * ZSTR + k0 + tg];
            float v0 = zr[0];              // row R1+g,   k0+tg
            float v1 = zr[8 * ZSTR];       // row R1+g+8, k0+tg
            float v2 = zr[4];              // row R1+g,   k0+tg+4
            float v3 = zr[8 * ZSTR + 4];   // row R1+g+8, k0+tg+4
            s0 += v0 + v2;  q0 += v0 * v0 + v2 * v2;
            s1 += v1 + v3;  q1 += v1 * v1 + v3 * v3;
            u32 afr[4];
            afr[0] = rna_tf32u(v0);
            afr[1] = rna_tf32u(v1);
            afr[2] = rna_tf32u(v2);
            afr[3] = rna_tf32u(v3);
            #pragma unroll
            for (int nt = 0; nt < 8; nt++) {
                const float* wr = &smf[W1_F + (k0 + tg) * W1STR + 8 * nt + g];
                u32 b0 = ldsf(wr);
                u32 b1 = ldsf(wr + 4 * W1STR);
                mma8(acc[nt], afr, b0, b1);
            }
        }

        // LN1 finalize (reduce over tg lanes)
        float m1a, r1a, m1b, r1b;
        {
            float sa = s0, qa = q0, sb = s1, qb = q1;
            sa += __shfl_xor_sync(0xffffffffu, sa, 1);
            qa += __shfl_xor_sync(0xffffffffu, qa, 1);
            sb += __shfl_xor_sync(0xffffffffu, sb, 1);
            qb += __shfl_xor_sync(0xffffffffu, qb, 1);
            sa += __shfl_xor_sync(0xffffffffu, sa, 2);
            qa += __shfl_xor_sync(0xffffffffu, qa, 2);
            sb += __shfl_xor_sync(0xffffffffu, sb, 2);
            qb += __shfl_xor_sync(0xffffffffu, qb, 2);
            m1a = sa * (1.f / TZ);
            float va = fmaxf(qa * (1.f / TZ) - m1a * m1a, 0.f);
            r1a = rsqrtf(va + EPSF);
            m1b = sb * (1.f / TZ);
            float vb_ = fmaxf(qb * (1.f / TZ) - m1b * m1b, 0.f);
            r1b = rsqrtf(vb_ + EPSF);
        }

        // ---- epilogue 1: LN1-fold + bin column + LN2 stats (warp-local) ----
        float s2a = 0.f, q2a = 0.f, s2b = 0.f, q2b = 0.f;
        #pragma unroll
        for (int nt = 0; nt < 8; nt++) {
            const int col = 8 * nt + 2 * tg;
            float2 Sv = *(const float2*)&smf[S_F + col];
            float2 Tv = *(const float2*)&smf[T_F + col];
            float2 W0 = *(const float2*)&smf[WAS_F + bin0 * TD + col];
            float2 W1v = *(const float2*)&smf[WAS_F + bin1 * TD + col];
            float v0 = r1a * (acc[nt][0] - m1a * Sv.x) + Tv.x + mk0 * W0.x;
            float v1 = r1a * (acc[nt][1] - m1a * Sv.y) + Tv.y + mk0 * W0.y;
            float v2 = r1b * (acc[nt][2] - m1b * Sv.x) + Tv.x + mk1 * W1v.x;
            float v3 = r1b * (acc[nt][3] - m1b * Sv.y) + Tv.y + mk1 * W1v.y;
            acc[nt][0] = v0; acc[nt][1] = v1; acc[nt][2] = v2; acc[nt][3] = v3;
            s2a += v0 + v1;  q2a += v0 * v0 + v1 * v1;
            s2b += v2 + v3;  q2b += v2 * v2 + v3 * v3;
        }
        // LN2 reduce over tg lanes (warp-local, no barrier)
        s2a += __shfl_xor_sync(0xffffffffu, s2a, 1);
        q2a += __shfl_xor_sync(0xffffffffu, q2a, 1);
        s2b += __shfl_xor_sync(0xffffffffu, s2b, 1);
        q2b += __shfl_xor_sync(0xffffffffu, q2b, 1);
        s2a += __shfl_xor_sync(0xffffffffu, s2a, 2);
        q2a += __shfl_xor_sync(0xffffffffu, q2a, 2);
        s2b += __shfl_xor_sync(0xffffffffu, s2b, 2);
        q2b += __shfl_xor_sync(0xffffffffu, q2b, 2);
        float m2a = s2a * (1.f / TD);
        float vva = fmaxf(q2a * (1.f / TD) - m2a * m2a, 0.f);
        float sca = 2.f * rsqrtf(4.f * vva + EPSF);    // exact v+v doubling
        float m2b = s2b * (1.f / TD);
        float vvb = fmaxf(q2b * (1.f / TD) - m2b * m2b, 0.f);
        float scb = 2.f * rsqrtf(4.f * vvb + EPSF);

        // ---- normalize + relu + tf32 -> vn ----
        // vn aliases zc with the SAME row stride (ZSTR): vn row r occupies cols 0..63
        // of zc row r — strictly warp-private aliasing (fixes the r9 race).
        float* vn = zc;
        #pragma unroll
        for (int nt = 0; nt < 8; nt++) {
            const int col = 8 * nt + 2 * tg;
            float2 gv = *(const float2*)&smf[VG_F + col];
            float2 bv = *(const float2*)&smf[VB_F + col];
            float2 ra, rb;
            ra.x = rna_tf32(fmaxf(fmaf((acc[nt][0] - m2a) * sca, gv.x, bv.x), 0.f));
            ra.y = rna_tf32(fmaxf(fmaf((acc[nt][1] - m2a) * sca, gv.y, bv.y), 0.f));
            rb.x = rna_tf32(fmaxf(fmaf((acc[nt][2] - m2b) * scb, gv.x, bv.x), 0.f));
            rb.y = rna_tf32(fmaxf(fmaf((acc[nt][3] - m2b) * scb, gv.y, bv.y), 0.f));
            *(float2*)&vn[(R1 + g) * ZSTR + col] = ra;
            *(float2*)&vn[(R1 + g + 8) * ZSTR + col] = rb;
        }
        __syncwarp();   // warp-private vn visibility

        // ---- GEMM2 (warp tile 16x128) + direct STG ----
        float acc2[16][4];
        #pragma unroll
        for (int b = 0; b < 16; b++)
            #pragma unroll
            for (int cI = 0; cI < 4; cI++) acc2[b][cI] = 0.f;

        #pragma unroll 2
        for (int ks = 0; ks < 8; ks++) {
            const int k0 = ks * 8;
            const float* vr = &vn[(R1 + g) * ZSTR + k0 + tg];
            u32 afr[4];
            afr[0] = ldsf(vr);
            afr[1] = ldsf(vr + 8 * ZSTR);
            afr[2] = ldsf(vr + 4);
            afr[3] = ldsf(vr + 8 * ZSTR + 4);
            #pragma unroll
            for (int nt = 0; nt < 16; nt++) {
                const float* wr = &smf[W2_F + (k0 + tg) * W2STR + 8 * nt + g];
                u32 b0 = ldsf(wr);
                u32 b1 = ldsf(wr + 4 * W2STR);
                mma8(acc2[nt], afr, b0, b1);
            }
        }
        // epilogue 2: STG.64 per C-pair (32B sectors fully covered)
        {
            const int ra = base_p + R1 + g;
            #pragma unroll
            for (int nt = 0; nt < 16; nt++) {
                const int col = 8 * nt + 2 * tg;
                *(float2*)&out[(size_t)ra * TZ + col] =
                    make_float2(acc2[nt][0], acc2[nt][1]);
                *(float2*)&out[(size_t)(ra + 8) * TZ + col] =
                    make_float2(acc2[nt][2], acc2[nt][3]);
            }
        }
        cur ^= 1;
    }
}

// ---------------- launch ----------------
extern "C" void kernel_launch(void* const* d_in, const int* in_sizes, int n_in,
                              void* d_out, int out_size) {
    const float* z   = (const float*)d_in[0];   // (1,1024,1024,128)
    const float* cc  = (const float*)d_in[1];   // (1,1024,3)
    const float* tdm = (const float*)d_in[2];   // (1,1024,1024)
    // d_in[3] = pair_mask (unused by reference)
    const float* Wz  = (const float*)d_in[4];   // (64,128)
    const float* Wa  = (const float*)d_in[5];   // (64,38)
    const float* Wu  = (const float*)d_in[6];   // (128,64)
    const float* zg  = (const float*)d_in[7];   // (128)
    const float* zb  = (const float*)d_in[8];   // (128)
    const float* vg  = (const float*)d_in[9];   // (64)
    const float* vb  = (const float*)d_in[10];  // (64)
    float* out = (float*)d_out;

    size_t smem_bytes = (size_t)SMEM_FLOATS * sizeof(float);
    cudaFuncSetAttribute(td_kernel, cudaFuncAttributeMaxDynamicSharedMemorySize, (int)smem_bytes);
    td_kernel<<<NBLOCKS, THREADS, smem_bytes>>>(z, cc, tdm, Wz, Wa, Wu, zg, zb, vg, vb, out);
}

// round 11
// speedup vs baseline: 1.3842x; 1.0165x over previous
#include <cuda_runtime.h>
#include <cstdint>

typedef uint32_t u32;

#define N_TOK 1024
#define TZ 128
#define TD 64
#define NB 38
#define EPSF 1e-5f
#define TM 128
#define THREADS 256
#define NBLOCKS 152
#define NTILES ((N_TOK * N_TOK) / TM)   // 8192

// smem strides (floats) — conflict-free fragment access
#define ZSTR 132     // ≡4 mod 32; also the vn stride (row-aligned aliasing)
#define W1STR 72     // ≡8 mod 32
#define W2STR 136    // ≡8 mod 32

// smem float offsets
#define ZA0_F 0                       // z/vn buf0 128x132
#define ZA1_F (TM * ZSTR)             // z/vn buf1
#define W1_F  (2 * TM * ZSTR)         // W1'[k][n] 128x72
#define W2_F  (W1_F + TZ * W1STR)     // W2 [d][c] 64x136
#define WAS_F (W2_F + TD * W2STR)     // Wa [bin][d] 38x64
#define S_F   (WAS_F + NB * TD)
#define T_F   (S_F + TD)
#define VG_F  (T_F + TD)
#define VB_F  (VG_F + TD)
#define SMEM_FLOATS (VB_F + TD)       // 54400 floats = 217.6 KB

// ---------------- helpers ----------------
__device__ __forceinline__ float rna_tf32(float x) {
    u32 r;
    asm("cvt.rna.tf32.f32 %0, %1;" : "=r"(r) : "f"(x));
    return __uint_as_float(r);
}
__device__ __forceinline__ u32 rna_tf32u(float x) {
    u32 r;
    asm("cvt.rna.tf32.f32 %0, %1;" : "=r"(r) : "f"(x));
    return r;
}
__device__ __forceinline__ void cpa16(float* dst, const void* g) {
    u32 a = (u32)__cvta_generic_to_shared(dst);
    asm volatile("cp.async.cg.shared.global [%0], [%1], 16;" :: "r"(a), "l"(g));
}
__device__ __forceinline__ void cpa_commit() { asm volatile("cp.async.commit_group;"); }
__device__ __forceinline__ void cpa_wait0() { asm volatile("cp.async.wait_group 0;" ::: "memory"); }

// D += A(16x8,row) * B(8x8,col), tf32
__device__ __forceinline__ void mma8(float* c, const u32* a, u32 b0, u32 b1) {
    asm volatile(
        "mma.sync.aligned.m16n8k8.row.col.f32.tf32.tf32.f32 "
        "{%0,%1,%2,%3}, {%4,%5,%6,%7}, {%8,%9}, {%0,%1,%2,%3};"
        : "+f"(c[0]), "+f"(c[1]), "+f"(c[2]), "+f"(c[3])
        : "r"(a[0]), "r"(a[1]), "r"(a[2]), "r"(a[3]), "r"(b0), "r"(b1));
}
__device__ __forceinline__ u32 ldsf(const float* p) { return __float_as_uint(*p); }

// ---------------- main fused kernel ----------------
__global__ __launch_bounds__(THREADS, 1)
void td_kernel(const float* __restrict__ z, const float* __restrict__ cc,
               const float* __restrict__ tdm, const float* __restrict__ Wz,
               const float* __restrict__ Wa, const float* __restrict__ Wu,
               const float* __restrict__ zg, const float* __restrict__ zb,
               const float* __restrict__ vg, const float* __restrict__ vb,
               float* __restrict__ out)
{
    extern __shared__ float smf[];
    const int t = threadIdx.x;
    const int wid = t >> 5, lane = t & 31;
    const int g = lane >> 2, tg = lane & 3;
    const bool isG1 = (wid < 4);

    // ---- prefetch first tile (all threads; overlaps weight staging) ----
    const int tile0 = blockIdx.x;
    {
        const float* src = z + (size_t)tile0 * TM * TZ;
        #pragma unroll
        for (int i = 0; i < 16; i++) {
            int e = i * THREADS + t;            // 0..4095 float4
            cpa16(&smf[ZA0_F + (e >> 5) * ZSTR + (e & 31) * 4], src + e * 4);
        }
        cpa_commit();
    }

    // ---- one-time weight staging ----
    for (int s = t; s < TZ * TD; s += THREADS) {        // W1'[k][n] = Wz[n][k]*zg[k]
        int k = s >> 6, n = s & 63;
        smf[W1_F + k * W1STR + n] = rna_tf32(Wz[n * TZ + k] * zg[k]);
    }
    for (int s = t; s < TD * TZ; s += THREADS) {        // W2[d][c] = Wu[c][d]
        int d = s >> 7, c = s & 127;
        smf[W2_F + d * W2STR + c] = rna_tf32(Wu[c * TD + d]);
    }
    for (int s = t; s < NB * TD; s += THREADS) {        // Was[bin][d]
        int k = s >> 6, d = s & 63;
        smf[WAS_F + k * TD + d] = Wa[d * NB + k];
    }
    if (t < TD) {
        float S = 0.f, T = 0.f;
        for (int k = 0; k < TZ; k++) {
            S += rna_tf32(Wz[t * TZ + k] * zg[k]);
            T += Wz[t * TZ + k] * zb[k];
        }
        smf[S_F + t] = S; smf[T_F + t] = T;
        smf[VG_F + t] = vg[t]; smf[VB_F + t] = vb[t];
    }

    const int R1 = (wid & 3) * 32;   // 32 rows per warp (role-dependent meaning)
    const int t2 = t & 127;          // index within group (for G2 prefetch)

    // number of G1 tiles for this block, +1 drain iteration
    const int ng1 = (NTILES - 1 - tile0) / NBLOCKS + 1;
    const int it_count = ng1 + 1;

    int tile = tile0;
    for (int it = 0; it < it_count; it++, tile += NBLOCKS) {
        const int cur = it & 1;
        float* bufc = &smf[cur ? ZA1_F : ZA0_F];     // z(tile) [G1 in], vn(tile) [G1 out]
        float* bufp = &smf[cur ? ZA0_F : ZA1_F];     // vn(tile-NBLOCKS) [G2 in], then z(tile+NBLOCKS)

        cpa_wait0();
        __syncthreads();   // publish: z(tile) in bufc, vn(tile-NBLOCKS) in bufp

        if (isG1) {
            if (tile < NTILES) {
                const int base_p = tile * TM;

                // ---- bins + mask for rows R1+g+8i ----
                int binr[4]; float mkr[4];
                {
                    const int i0 = base_p >> 10;
                    const int jb = base_p & (N_TOK - 1);
                    const float cx = __ldg(cc + i0 * 3 + 0);
                    const float cy = __ldg(cc + i0 * 3 + 1);
                    const float cz = __ldg(cc + i0 * 3 + 2);
                    #pragma unroll
                    for (int i = 0; i < 4; i++) {
                        const int row = R1 + g + 8 * i;
                        const int j0 = jb + row;
                        float dx = cx - __ldg(cc + j0 * 3 + 0);
                        float dy = cy - __ldg(cc + j0 * 3 + 1);
                        float dz = cz - __ldg(cc + j0 * 3 + 2);
                        float dist = sqrtf(dx * dx + dy * dy + dz * dz);
                        int idx = 0;
                        #pragma unroll
                        for (int k = 0; k < NB - 1; k++) {
                            float b = (float)(3.25 + k * (47.5 / 36.0));
                            idx += (dist > b) ? 1 : 0;
                        }
                        binr[i] = idx;
                        mkr[i] = __ldg(tdm + base_p + row);
                    }
                }

                // ---- GEMM1 (warp tile 32x64) + fused LN1 stats ----
                float acc[2][8][4];
                #pragma unroll
                for (int a = 0; a < 2; a++)
                    #pragma unroll
                    for (int b = 0; b < 8; b++)
                        #pragma unroll
                        for (int cI = 0; cI < 4; cI++) acc[a][b][cI] = 0.f;
                float ss[4] = {0.f, 0.f, 0.f, 0.f};
                float qq[4] = {0.f, 0.f, 0.f, 0.f};

                #pragma unroll 4
                for (int ks = 0; ks < 16; ks++) {
                    const int k0 = ks * 8;
                    u32 afr[2][4];
                    #pragma unroll
                    for (int rt = 0; rt < 2; rt++) {
                        const float* zr = &bufc[(R1 + 16 * rt + g) * ZSTR + k0 + tg];
                        float v0 = zr[0];
                        float v1 = zr[8 * ZSTR];
                        float v2 = zr[4];
                        float v3 = zr[8 * ZSTR + 4];
                        ss[2 * rt + 0] += v0 + v2;  qq[2 * rt + 0] += v0 * v0 + v2 * v2;
                        ss[2 * rt + 1] += v1 + v3;  qq[2 * rt + 1] += v1 * v1 + v3 * v3;
                        afr[rt][0] = rna_tf32u(v0);
                        afr[rt][1] = rna_tf32u(v1);
                        afr[rt][2] = rna_tf32u(v2);
                        afr[rt][3] = rna_tf32u(v3);
                    }
                    #pragma unroll
                    for (int nt = 0; nt < 8; nt++) {
                        const float* wr = &smf[W1_F + (k0 + tg) * W1STR + 8 * nt + g];
                        u32 b0 = ldsf(wr);
                        u32 b1 = ldsf(wr + 4 * W1STR);
                        mma8(acc[0][nt], afr[0], b0, b1);
                        mma8(acc[1][nt], afr[1], b0, b1);
                    }
                }

                // ---- per-slot LN1 finalize, epi1, LN2, vn write ----
                #pragma unroll
                for (int i = 0; i < 4; i++) {
                    const int rt = i >> 1, cp = (i & 1) * 2;
                    const int row = R1 + g + 8 * i;
                    float s = ss[i], q = qq[i];
                    s += __shfl_xor_sync(0xffffffffu, s, 1);
                    q += __shfl_xor_sync(0xffffffffu, q, 1);
                    s += __shfl_xor_sync(0xffffffffu, s, 2);
                    q += __shfl_xor_sync(0xffffffffu, q, 2);
                    float m1 = s * (1.f / TZ);
                    float var1 = fmaxf(q * (1.f / TZ) - m1 * m1, 0.f);
                    float r1 = rsqrtf(var1 + EPSF);
                    const float mk = mkr[i];
                    const int bin = binr[i];

                    float s2 = 0.f, q2 = 0.f;
                    #pragma unroll
                    for (int nt = 0; nt < 8; nt++) {
                        const int col = 8 * nt + 2 * tg;
                        float2 Sv = *(const float2*)&smf[S_F + col];
                        float2 Tv = *(const float2*)&smf[T_F + col];
                        float2 Wv = *(const float2*)&smf[WAS_F + bin * TD + col];
                        float v0 = r1 * (acc[rt][nt][cp]     - m1 * Sv.x) + Tv.x + mk * Wv.x;
                        float v1 = r1 * (acc[rt][nt][cp + 1] - m1 * Sv.y) + Tv.y + mk * Wv.y;
                        acc[rt][nt][cp] = v0; acc[rt][nt][cp + 1] = v1;
                        s2 += v0 + v1;  q2 += v0 * v0 + v1 * v1;
                    }
                    s2 += __shfl_xor_sync(0xffffffffu, s2, 1);
                    q2 += __shfl_xor_sync(0xffffffffu, q2, 1);
                    s2 += __shfl_xor_sync(0xffffffffu, s2, 2);
                    q2 += __shfl_xor_sync(0xffffffffu, q2, 2);
                    float m2 = s2 * (1.f / TD);
                    float var2 = fmaxf(q2 * (1.f / TD) - m2 * m2, 0.f);
                    float sc = 2.f * rsqrtf(4.f * var2 + EPSF);   // exact v+v doubling

                    #pragma unroll
                    for (int nt = 0; nt < 8; nt++) {
                        const int col = 8 * nt + 2 * tg;
                        float2 gv = *(const float2*)&smf[VG_F + col];
                        float2 bv = *(const float2*)&smf[VB_F + col];
                        float2 r;
                        r.x = rna_tf32(fmaxf(fmaf((acc[rt][nt][cp]     - m2) * sc, gv.x, bv.x), 0.f));
                        r.y = rna_tf32(fmaxf(fmaf((acc[rt][nt][cp + 1] - m2) * sc, gv.y, bv.y), 0.f));
                        *(float2*)&bufc[row * ZSTR + col] = r;   // vn: row-aligned alias
                    }
                }
            }
        } else {
            // ================= G2 warps: GEMM2 on vn(tile-NBLOCKS) =================
            if (it > 0) {
                const int base_p = (tile - NBLOCKS) * TM;
                #pragma unroll
                for (int pass = 0; pass < 2; pass++) {
                    const int C2 = pass * 64;
                    float acc2[2][8][4];
                    #pragma unroll
                    for (int a = 0; a < 2; a++)
                        #pragma unroll
                        for (int b = 0; b < 8; b++)
                            #pragma unroll
                            for (int cI = 0; cI < 4; cI++) acc2[a][b][cI] = 0.f;

                    #pragma unroll 2
                    for (int ks = 0; ks < 8; ks++) {
                        const int k0 = ks * 8;
                        u32 afr[2][4];
                        #pragma unroll
                        for (int rt = 0; rt < 2; rt++) {
                            const float* vr = &bufp[(R1 + 16 * rt + g) * ZSTR + k0 + tg];
                            afr[rt][0] = ldsf(vr);
                            afr[rt][1] = ldsf(vr + 8 * ZSTR);
                            afr[rt][2] = ldsf(vr + 4);
                            afr[rt][3] = ldsf(vr + 8 * ZSTR + 4);
                        }
                        #pragma unroll
                        for (int nt = 0; nt < 8; nt++) {
                            const float* wr = &smf[W2_F + (k0 + tg) * W2STR + C2 + 8 * nt + g];
                            u32 b0 = ldsf(wr);
                            u32 b1 = ldsf(wr + 4 * W2STR);
                            mma8(acc2[0][nt], afr[0], b0, b1);
                            mma8(acc2[1][nt], afr[1], b0, b1);
                        }
                    }
                    #pragma unroll
                    for (int rt = 0; rt < 2; rt++) {
                        const int ra = base_p + R1 + 16 * rt + g;
                        #pragma unroll
                        for (int nt = 0; nt < 8; nt++) {
                            const int col = C2 + 8 * nt + 2 * tg;
                            *(float2*)&out[(size_t)ra * TZ + col] =
                                make_float2(acc2[rt][nt][0], acc2[rt][nt][1]);
                            *(float2*)&out[(size_t)(ra + 8) * TZ + col] =
                                make_float2(acc2[rt][nt][2], acc2[rt][nt][3]);
                        }
                    }
                }
            }
            // all G2 vn reads done -> safe to overwrite bufp with next z
            asm volatile("bar.sync 1, 128;" ::: "memory");
            const int tile_next = tile + NBLOCKS;
            if (tile_next < NTILES) {
                const float* src = z + (size_t)tile_next * TM * TZ;
                #pragma unroll
                for (int i = 0; i < 32; i++) {
                    int e = i * 128 + t2;
                    cpa16(&bufp[(e >> 5) * ZSTR + (e & 31) * 4], src + e * 4);
                }
                cpa_commit();
            }
        }
    }
}

// ---------------- launch ----------------
extern "C" void kernel_launch(void* const* d_in, const int* in_sizes, int n_in,
                              void* d_out, int out_size) {
    const float* z   = (const float*)d_in[0];   // (1,1024,1024,128)
    const float* cc  = (const float*)d_in[1];   // (1,1024,3)
    const float* tdm = (const float*)d_in[2];   // (1,1024,1024)
    // d_in[3] = pair_mask (unused by reference)
    const float* Wz  = (const float*)d_in[4];   // (64,128)
    const float* Wa  = (const float*)d_in[5];   // (64,38)
    const float* Wu  = (const float*)d_in[6];   // (128,64)
    const float* zg  = (const float*)d_in[7];   // (128)
    const float* zb  = (const float*)d_in[8];   // (128)
    const float* vg  = (const float*)d_in[9];   // (64)
    const float* vb  = (const float*)d_in[10];  // (64)
    float* out = (float*)d_out;

    size_t smem_bytes = (size_t)SMEM_FLOATS * sizeof(float);
    cudaFuncSetAttribute(td_kernel, cudaFuncAttributeMaxDynamicSharedMemorySize, (int)smem_bytes);
    td_kernel<<<NBLOCKS, THREADS, smem_bytes>>>(z, cc, tdm, Wz, Wa, Wu, zg, zb, vg, vb, out);
}

// round 13
// speedup vs baseline: 1.4762x; 1.0665x over previous
#include <cuda_runtime.h>
#include <cstdint>

typedef uint32_t u32;

#define N_TOK 1024
#define TZ 128
#define TD 64
#define NB 38
#define EPSF 1e-5f
#define TM 128
#define THREADS 512
#define NBLOCKS 152
#define NTILES ((N_TOK * N_TOK) / TM)   // 8192

// smem strides (floats) — conflict-free fragment access
#define ZSTR 132     // ≡4 mod 32; also the vn stride (row-aligned aliasing)
#define W1STR 72     // ≡8 mod 32
#define W2STR 136    // ≡8 mod 32

// smem float offsets
#define ZA0_F 0                       // z/vn buf0 128x132
#define ZA1_F (TM * ZSTR)             // z/vn buf1
#define W1_F  (2 * TM * ZSTR)         // W1'[k][n] 128x72
#define W2_F  (W1_F + TZ * W1STR)     // W2 [d][c] 64x136
#define WAS_F (W2_F + TD * W2STR)     // Wa [bin][d] 38x64
#define S_F   (WAS_F + NB * TD)
#define T_F   (S_F + TD)
#define VG_F  (T_F + TD)
#define VB_F  (VG_F + TD)
#define SMEM_FLOATS (VB_F + TD)       // 54400 floats = 217.6 KB

// ---------------- helpers ----------------
__device__ __forceinline__ float rna_tf32(float x) {
    u32 r;
    asm("cvt.rna.tf32.f32 %0, %1;" : "=r"(r) : "f"(x));
    return __uint_as_float(r);
}
__device__ __forceinline__ u32 rna_tf32u(float x) {
    u32 r;
    asm("cvt.rna.tf32.f32 %0, %1;" : "=r"(r) : "f"(x));
    return r;
}
__device__ __forceinline__ void cpa16(float* dst, const void* g) {
    u32 a = (u32)__cvta_generic_to_shared(dst);
    asm volatile("cp.async.cg.shared.global [%0], [%1], 16;" :: "r"(a), "l"(g));
}
__device__ __forceinline__ void cpa_commit() { asm volatile("cp.async.commit_group;"); }
__device__ __forceinline__ void cpa_wait0() { asm volatile("cp.async.wait_group 0;" ::: "memory"); }

// D += A(16x8,row) * B(8x8,col), tf32
__device__ __forceinline__ void mma8(float* c, const u32* a, u32 b0, u32 b1) {
    asm volatile(
        "mma.sync.aligned.m16n8k8.row.col.f32.tf32.tf32.f32 "
        "{%0,%1,%2,%3}, {%4,%5,%6,%7}, {%8,%9}, {%0,%1,%2,%3};"
        : "+f"(c[0]), "+f"(c[1]), "+f"(c[2]), "+f"(c[3])
        : "r"(a[0]), "r"(a[1]), "r"(a[2]), "r"(a[3]), "r"(b0), "r"(b1));
}
__device__ __forceinline__ u32 ldsf(const float* p) { return __float_as_uint(*p); }

// ---------------- main fused kernel ----------------
__global__ __launch_bounds__(THREADS, 1)
void td_kernel(const float* __restrict__ z, const float* __restrict__ cc,
               const float* __restrict__ tdm, const float* __restrict__ Wz,
               const float* __restrict__ Wa, const float* __restrict__ Wu,
               const float* __restrict__ zg, const float* __restrict__ zb,
               const float* __restrict__ vg, const float* __restrict__ vb,
               float* __restrict__ out)
{
    extern __shared__ float smf[];
    const int t = threadIdx.x;
    const int wid = t >> 5, lane = t & 31;
    const int g = lane >> 2, tg = lane & 3;
    const bool isG1 = (wid < 8);
    const int R1 = (wid & 7) * 16;   // 16 rows per warp in both roles
    const int t2 = t & 255;          // index within 256-thread group

    // ---- prefetch first tile (all 512 threads; overlaps weight staging) ----
    const int tile0 = blockIdx.x;
    {
        const float* src = z + (size_t)tile0 * TM * TZ;
        #pragma unroll
        for (int i = 0; i < 8; i++) {
            int e = i * THREADS + t;            // 0..4095 float4
            cpa16(&smf[ZA0_F + (e >> 5) * ZSTR + (e & 31) * 4], src + e * 4);
        }
        cpa_commit();
    }

    // ---- one-time weight staging ----
    for (int s = t; s < TZ * TD; s += THREADS) {        // W1'[k][n] = Wz[n][k]*zg[k]
        int k = s >> 6, n = s & 63;
        smf[W1_F + k * W1STR + n] = rna_tf32(Wz[n * TZ + k] * zg[k]);
    }
    for (int s = t; s < TD * TZ; s += THREADS) {        // W2[d][c] = Wu[c][d]
        int d = s >> 7, c = s & 127;
        smf[W2_F + d * W2STR + c] = rna_tf32(Wu[c * TD + d]);
    }
    for (int s = t; s < NB * TD; s += THREADS) {        // Was[bin][d]
        int k = s >> 6, d = s & 63;
        smf[WAS_F + k * TD + d] = Wa[d * NB + k];
    }
    if (t < TD) {
        float S = 0.f, T = 0.f;
        for (int k = 0; k < TZ; k++) {
            S += rna_tf32(Wz[t * TZ + k] * zg[k]);
            T += Wz[t * TZ + k] * zb[k];
        }
        smf[S_F + t] = S; smf[T_F + t] = T;
        smf[VG_F + t] = vg[t]; smf[VB_F + t] = vb[t];
    }

    // number of G1 tiles for this block, +1 drain iteration
    const int ng1 = (NTILES - 1 - tile0) / NBLOCKS + 1;
    const int it_count = ng1 + 1;

    int tile = tile0;
    for (int it = 0; it < it_count; it++, tile += NBLOCKS) {
        const int cur = it & 1;
        float* bufc = &smf[cur ? ZA1_F : ZA0_F];     // z(tile) [G1 in], vn(tile) [G1 out]
        float* bufp = &smf[cur ? ZA0_F : ZA1_F];     // vn(tile-NBLOCKS) [G2 in], then z(tile+NBLOCKS)

        cpa_wait0();
        __syncthreads();   // publish: z(tile) in bufc, vn(tile-NBLOCKS) in bufp

        if (isG1) {
            if (tile < NTILES) {
                const int base_p = tile * TM;

                // ---- bins + mask for rows R1+g, R1+g+8 ----
                int bin0, bin1;
                float mk0, mk1;
                {
                    const int i0 = base_p >> 10;
                    const int jb = base_p & (N_TOK - 1);
                    const float cx = __ldg(cc + i0 * 3 + 0);
                    const float cy = __ldg(cc + i0 * 3 + 1);
                    const float cz = __ldg(cc + i0 * 3 + 2);
                    #pragma unroll
                    for (int i = 0; i < 2; i++) {
                        const int row = R1 + g + 8 * i;
                        const int j0 = jb + row;
                        float dx = cx - __ldg(cc + j0 * 3 + 0);
                        float dy = cy - __ldg(cc + j0 * 3 + 1);
                        float dz = cz - __ldg(cc + j0 * 3 + 2);
                        float dist = sqrtf(dx * dx + dy * dy + dz * dz);
                        int idx = 0;
                        #pragma unroll
                        for (int k = 0; k < NB - 1; k++) {
                            float b = (float)(3.25 + k * (47.5 / 36.0));
                            idx += (dist > b) ? 1 : 0;
                        }
                        if (i == 0) { bin0 = idx; mk0 = __ldg(tdm + base_p + row); }
                        else        { bin1 = idx; mk1 = __ldg(tdm + base_p + row); }
                    }
                }

                // ---- GEMM1 (warp tile 16x64) + fused LN1 stats ----
                float acc[8][4];
                #pragma unroll
                for (int b = 0; b < 8; b++)
                    #pragma unroll
                    for (int cI = 0; cI < 4; cI++) acc[b][cI] = 0.f;
                float s0 = 0.f, q0 = 0.f, s1 = 0.f, q1 = 0.f;

                #pragma unroll 4
                for (int ks = 0; ks < 16; ks++) {
                    const int k0 = ks * 8;
                    const float* zr = &bufc[(R1 + g) * ZSTR + k0 + tg];
                    float v0 = zr[0];
                    float v1 = zr[8 * ZSTR];
                    float v2 = zr[4];
                    float v3 = zr[8 * ZSTR + 4];
                    s0 += v0 + v2;  q0 += v0 * v0 + v2 * v2;
                    s1 += v1 + v3;  q1 += v1 * v1 + v3 * v3;
                    u32 afr[4];
                    afr[0] = rna_tf32u(v0);
                    afr[1] = rna_tf32u(v1);
                    afr[2] = rna_tf32u(v2);
                    afr[3] = rna_tf32u(v3);
                    #pragma unroll
                    for (int nt = 0; nt < 8; nt++) {
                        const float* wr = &smf[W1_F + (k0 + tg) * W1STR + 8 * nt + g];
                        u32 b0 = ldsf(wr);
                        u32 b1 = ldsf(wr + 4 * W1STR);
                        mma8(acc[nt], afr, b0, b1);
                    }
                }

                // LN1 finalize (reduce over tg lanes)
                float m1a, r1a, m1b, r1b;
                {
                    float sa = s0, qa = q0, sb = s1, qb = q1;
                    sa += __shfl_xor_sync(0xffffffffu, sa, 1);
                    qa += __shfl_xor_sync(0xffffffffu, qa, 1);
                    sb += __shfl_xor_sync(0xffffffffu, sb, 1);
                    qb += __shfl_xor_sync(0xffffffffu, qb, 1);
                    sa += __shfl_xor_sync(0xffffffffu, sa, 2);
                    qa += __shfl_xor_sync(0xffffffffu, qa, 2);
                    sb += __shfl_xor_sync(0xffffffffu, sb, 2);
                    qb += __shfl_xor_sync(0xffffffffu, qb, 2);
                    m1a = sa * (1.f / TZ);
                    float va = fmaxf(qa * (1.f / TZ) - m1a * m1a, 0.f);
                    r1a = rsqrtf(va + EPSF);
                    m1b = sb * (1.f / TZ);
                    float vb_ = fmaxf(qb * (1.f / TZ) - m1b * m1b, 0.f);
                    r1b = rsqrtf(vb_ + EPSF);
                }

                // ---- epilogue 1: LN1-fold + bin column + LN2 stats (warp-local) ----
                float s2a = 0.f, q2a = 0.f, s2b = 0.f, q2b = 0.f;
                #pragma unroll
                for (int nt = 0; nt < 8; nt++) {
                    const int col = 8 * nt + 2 * tg;
                    float2 Sv = *(const float2*)&smf[S_F + col];
                    float2 Tv = *(const float2*)&smf[T_F + col];
                    float2 W0 = *(const float2*)&smf[WAS_F + bin0 * TD + col];
                    float2 W1v = *(const float2*)&smf[WAS_F + bin1 * TD + col];
                    float v0 = r1a * (acc[nt][0] - m1a * Sv.x) + Tv.x + mk0 * W0.x;
                    float v1 = r1a * (acc[nt][1] - m1a * Sv.y) + Tv.y + mk0 * W0.y;
                    float v2 = r1b * (acc[nt][2] - m1b * Sv.x) + Tv.x + mk1 * W1v.x;
                    float v3 = r1b * (acc[nt][3] - m1b * Sv.y) + Tv.y + mk1 * W1v.y;
                    acc[nt][0] = v0; acc[nt][1] = v1; acc[nt][2] = v2; acc[nt][3] = v3;
                    s2a += v0 + v1;  q2a += v0 * v0 + v1 * v1;
                    s2b += v2 + v3;  q2b += v2 * v2 + v3 * v3;
                }
                s2a += __shfl_xor_sync(0xffffffffu, s2a, 1);
                q2a += __shfl_xor_sync(0xffffffffu, q2a, 1);
                s2b += __shfl_xor_sync(0xffffffffu, s2b, 1);
                q2b += __shfl_xor_sync(0xffffffffu, q2b, 1);
                s2a += __shfl_xor_sync(0xffffffffu, s2a, 2);
                q2a += __shfl_xor_sync(0xffffffffu, q2a, 2);
                s2b += __shfl_xor_sync(0xffffffffu, s2b, 2);
                q2b += __shfl_xor_sync(0xffffffffu, q2b, 2);
                float m2a = s2a * (1.f / TD);
                float vva = fmaxf(q2a * (1.f / TD) - m2a * m2a, 0.f);
                float sca = 2.f * rsqrtf(4.f * vva + EPSF);    // exact v+v doubling
                float m2b = s2b * (1.f / TD);
                float vvb = fmaxf(q2b * (1.f / TD) - m2b * m2b, 0.f);
                float scb = 2.f * rsqrtf(4.f * vvb + EPSF);

                // ---- normalize + relu + tf32 -> vn (row-aligned alias of bufc) ----
                #pragma unroll
                for (int nt = 0; nt < 8; nt++) {
                    const int col = 8 * nt + 2 * tg;
                    float2 gv = *(const float2*)&smf[VG_F + col];
                    float2 bv = *(const float2*)&smf[VB_F + col];
                    float2 ra, rb;
                    ra.x = rna_tf32(fmaxf(fmaf((acc[nt][0] - m2a) * sca, gv.x, bv.x), 0.f));
                    ra.y = rna_tf32(fmaxf(fmaf((acc[nt][1] - m2a) * sca, gv.y, bv.y), 0.f));
                    rb.x = rna_tf32(fmaxf(fmaf((acc[nt][2] - m2b) * scb, gv.x, bv.x), 0.f));
                    rb.y = rna_tf32(fmaxf(fmaf((acc[nt][3] - m2b) * scb, gv.y, bv.y), 0.f));
                    *(float2*)&bufc[(R1 + g) * ZSTR + col] = ra;
                    *(float2*)&bufc[(R1 + g + 8) * ZSTR + col] = rb;
                }
            }
        } else {
            // ================= G2 warps: GEMM2 (16x128) on vn(tile-NBLOCKS) =================
            if (it > 0) {
                const int base_p = (tile - NBLOCKS) * TM;
                float acc2[16][4];
                #pragma unroll
                for (int b = 0; b < 16; b++)
                    #pragma unroll
                    for (int cI = 0; cI < 4; cI++) acc2[b][cI] = 0.f;

                #pragma unroll 2
                for (int ks = 0; ks < 8; ks++) {
                    const int k0 = ks * 8;
                    const float* vr = &bufp[(R1 + g) * ZSTR + k0 + tg];
                    u32 afr[4];
                    afr[0] = ldsf(vr);
                    afr[1] = ldsf(vr + 8 * ZSTR);
                    afr[2] = ldsf(vr + 4);
                    afr[3] = ldsf(vr + 8 * ZSTR + 4);
                    #pragma unroll
                    for (int nt = 0; nt < 16; nt++) {
                        const float* wr = &smf[W2_F + (k0 + tg) * W2STR + 8 * nt + g];
                        u32 b0 = ldsf(wr);
                        u32 b1 = ldsf(wr + 4 * W2STR);
                        mma8(acc2[nt], afr, b0, b1);
                    }
                }
                {
                    const int ra = base_p + R1 + g;
                    #pragma unroll
                    for (int nt = 0; nt < 16; nt++) {
                        const int col = 8 * nt + 2 * tg;
                        *(float2*)&out[(size_t)ra * TZ + col] =
                            make_float2(acc2[nt][0], acc2[nt][1]);
                        *(float2*)&out[(size_t)(ra + 8) * TZ + col] =
                            make_float2(acc2[nt][2], acc2[nt][3]);
                    }
                }
            }
            // all G2 vn reads done -> safe to overwrite bufp with next z
            asm volatile("bar.sync 1, 256;" ::: "memory");
            const int tile_next = tile + NBLOCKS;
            if (tile_next < NTILES) {
                const float* src = z + (size_t)tile_next * TM * TZ;
                #pragma unroll
                for (int i = 0; i < 16; i++) {
                    int e = i * 256 + t2;
                    cpa16(&bufp[(e >> 5) * ZSTR + (e & 31) * 4], src + e * 4);
                }
                cpa_commit();
            }
        }
    }
}

// ---------------- launch ----------------
extern "C" void kernel_launch(void* const* d_in, const int* in_sizes, int n_in,
                              void* d_out, int out_size) {
    const float* z   = (const float*)d_in[0];   // (1,1024,1024,128)
    const float* cc  = (const float*)d_in[1];   // (1,1024,3)
    const float* tdm = (const float*)d_in[2];   // (1,1024,1024)
    // d_in[3] = pair_mask (unused by reference)
    const float* Wz  = (const float*)d_in[4];   // (64,128)
    const float* Wa  = (const float*)d_in[5];   // (64,38)
    const float* Wu  = (const float*)d_in[6];   // (128,64)
    const float* zg  = (const float*)d_in[7];   // (128)
    const float* zb  = (const float*)d_in[8];   // (128)
    const float* vg  = (const float*)d_in[9];   // (64)
    const float* vb  = (const float*)d_in[10];  // (64)
    float* out = (float*)d_out;

    size_t smem_bytes = (size_t)SMEM_FLOATS * sizeof(float);
    cudaFuncSetAttribute(td_kernel, cudaFuncAttributeMaxDynamicSharedMemorySize, (int)smem_bytes);
    td_kernel<<<NBLOCKS, THREADS, smem_bytes>>>(z, cc, tdm, Wz, Wa, Wu, zg, zb, vg, vb, out);
}

// round 14
// speedup vs baseline: 2.0580x; 1.3941x over previous
#include <cuda_runtime.h>
#include <cuda_fp16.h>
#include <cstdint>

typedef uint32_t u32;

#define N_TOK 1024
#define TZ 128
#define TD 64
#define NB 38
#define EPSF 1e-5f
#define TM 128
#define THREADS 512
#define NBLOCKS 152
#define NTILES ((N_TOK * N_TOK) / TM)   // 8192

// strides (4-byte units) — conflict-free fragment access
#define ZSTR 136     // f32; ≡8 mod 32: float2 A-loads conflict-free per half-warp phase
#define VNSTR 36     // u32 half2; ≡4 mod 32: u32 lane pattern 4g+tg distinct
#define W1STR 72     // u32 half2; ≡8 mod 32: lane pattern 8tg+g distinct
#define W2STR 136    // u32 half2; ≡8 mod 32

// smem offsets (4-byte units)
#define ZA0_F 0                         // z f32 buf0: 128*136
#define ZA1_F (TM * ZSTR)               // z f32 buf1
#define VN0_F (2 * TM * ZSTR)           // vn half2 buf0: 128*36
#define VN1_F (VN0_F + TM * VNSTR)      // vn half2 buf1
#define W1H_F (VN1_F + TM * VNSTR)      // W1 half2 [64 kp][72]
#define W2H_F (W1H_F + 64 * W1STR)      // W2 half2 [32 kp][136]
#define WAS_F (W2H_F + 32 * W2STR)      // Wa f32 [bin][d] 38x64
#define S_F   (WAS_F + NB * TD)
#define T_F   (S_F + TD)
#define VG_F  (T_F + TD)
#define VB_F  (VG_F + TD)
#define SMEM_FLOATS (VB_F + TD)         // 55680 * 4B = 222720 B

// ---------------- helpers ----------------
__device__ __forceinline__ u32 packh2(float lo, float hi) {
    half2 h = __floats2half2_rn(lo, hi);      // .x = lo (low 16 bits)
    return *(u32*)&h;
}
__device__ __forceinline__ void cpa16(float* dst, const void* g) {
    u32 a = (u32)__cvta_generic_to_shared(dst);
    asm volatile("cp.async.cg.shared.global [%0], [%1], 16;" :: "r"(a), "l"(g));
}
__device__ __forceinline__ void cpa_commit() { asm volatile("cp.async.commit_group;"); }
__device__ __forceinline__ void cpa_wait0() { asm volatile("cp.async.wait_group 0;" ::: "memory"); }

// D += A(16x16,row) * B(16x8,col), fp16 inputs, f32 accum
__device__ __forceinline__ void mma16(float* c, const u32* a, u32 b0, u32 b1) {
    asm volatile(
        "mma.sync.aligned.m16n8k16.row.col.f32.f16.f16.f32 "
        "{%0,%1,%2,%3}, {%4,%5,%6,%7}, {%8,%9}, {%0,%1,%2,%3};"
        : "+f"(c[0]), "+f"(c[1]), "+f"(c[2]), "+f"(c[3])
        : "r"(a[0]), "r"(a[1]), "r"(a[2]), "r"(a[3]), "r"(b0), "r"(b1));
}

// ---------------- main fused kernel ----------------
__global__ __launch_bounds__(THREADS, 1)
void td_kernel(const float* __restrict__ z, const float* __restrict__ cc,
               const float* __restrict__ tdm, const float* __restrict__ Wz,
               const float* __restrict__ Wa, const float* __restrict__ Wu,
               const float* __restrict__ zg, const float* __restrict__ zb,
               const float* __restrict__ vg, const float* __restrict__ vb,
               float* __restrict__ out)
{
    extern __shared__ float smf[];
    u32* smu = (u32*)smf;
    const int t = threadIdx.x;
    const int wid = t >> 5, lane = t & 31;
    const int g = lane >> 2, tg = lane & 3;
    const bool isG1 = (wid < 8);
    const int R1 = (wid & 7) * 16;
    const int t2 = t & 255;

    // ---- prefetch first tile (all 512 threads) ----
    const int tile0 = blockIdx.x;
    {
        const float* src = z + (size_t)tile0 * TM * TZ;
        #pragma unroll
        for (int i = 0; i < 8; i++) {
            int e = i * THREADS + t;            // 0..4095 float4
            cpa16(&smf[ZA0_F + (e >> 5) * ZSTR + (e & 31) * 4], src + e * 4);
        }
        cpa_commit();
    }

    // ---- one-time weight staging ----
    // W1 half2: w1h[kp][n] = {Wz[n][2kp]*zg[2kp], Wz[n][2kp+1]*zg[2kp+1]}
    for (int s = t; s < 64 * TD; s += THREADS) {
        int kp = s >> 6, n = s & 63;
        float lo = Wz[n * TZ + 2 * kp]     * zg[2 * kp];
        float hi = Wz[n * TZ + 2 * kp + 1] * zg[2 * kp + 1];
        smu[W1H_F + kp * W1STR + n] = packh2(lo, hi);
    }
    // W2 half2: w2h[kp][c] = {Wu[c][2kp], Wu[c][2kp+1]}
    for (int s = t; s < 32 * TZ; s += THREADS) {
        int kp = s >> 7, c = s & 127;
        smu[W2H_F + kp * W2STR + c] = packh2(Wu[c * TD + 2 * kp], Wu[c * TD + 2 * kp + 1]);
    }
    for (int s = t; s < NB * TD; s += THREADS) {
        int k = s >> 6, d = s & 63;
        smf[WAS_F + k * TD + d] = Wa[d * NB + k];
    }
    if (t < TD) {
        float S = 0.f, T = 0.f;
        for (int k = 0; k < TZ; k++) {
            S += __half2float(__float2half_rn(Wz[t * TZ + k] * zg[k]));
            T += Wz[t * TZ + k] * zb[k];
        }
        smf[S_F + t] = S; smf[T_F + t] = T;
        smf[VG_F + t] = vg[t]; smf[VB_F + t] = vb[t];
    }

    const int ng1 = (NTILES - 1 - tile0) / NBLOCKS + 1;
    const int it_count = ng1 + 1;        // +1 drain iteration

    int tile = tile0;
    for (int it = 0; it < it_count; it++, tile += NBLOCKS) {
        const int cur = it & 1;
        float* zc   = &smf[cur ? ZA1_F : ZA0_F];       // z(tile)            [G1 in]
        u32* vncur  = &smu[cur ? VN1_F : VN0_F];       // vn(tile)           [G1 out]
        u32* vnprev = &smu[cur ? VN0_F : VN1_F];       // vn(tile-NBLOCKS)   [G2 in]
        float* znxt = &smf[cur ? ZA0_F : ZA1_F];       // z(tile+NBLOCKS)    [prefetch dst]

        cpa_wait0();
        __syncthreads();   // single block barrier per iteration

        if (isG1) {
            if (tile < NTILES) {
                const int base_p = tile * TM;

                // ---- bins + mask (rows R1+g, R1+g+8) ----
                int bin0, bin1;
                float mk0, mk1;
                {
                    const int i0 = base_p >> 10;
                    const int jb = base_p & (N_TOK - 1);
                    const float cx = __ldg(cc + i0 * 3 + 0);
                    const float cy = __ldg(cc + i0 * 3 + 1);
                    const float cz = __ldg(cc + i0 * 3 + 2);
                    #pragma unroll
                    for (int i = 0; i < 2; i++) {
                        const int row = R1 + g + 8 * i;
                        const int j0 = jb + row;
                        float dx = cx - __ldg(cc + j0 * 3 + 0);
                        float dy = cy - __ldg(cc + j0 * 3 + 1);
                        float dz = cz - __ldg(cc + j0 * 3 + 2);
                        float dist = sqrtf(dx * dx + dy * dy + dz * dz);
                        int idx = 0;
                        #pragma unroll
                        for (int k = 0; k < NB - 1; k++) {
                            float b = (float)(3.25 + k * (47.5 / 36.0));
                            idx += (dist > b) ? 1 : 0;
                        }
                        if (i == 0) { bin0 = idx; mk0 = __ldg(tdm + base_p + row); }
                        else        { bin1 = idx; mk1 = __ldg(tdm + base_p + row); }
                    }
                }

                // ---- GEMM1 fp16 (warp tile 16x64, 8 k16-steps) + LN1 stats ----
                float acc[8][4];
                #pragma unroll
                for (int b = 0; b < 8; b++)
                    #pragma unroll
                    for (int cI = 0; cI < 4; cI++) acc[b][cI] = 0.f;
                float s0 = 0.f, q0 = 0.f, s1 = 0.f, q1 = 0.f;

                #pragma unroll
                for (int ks = 0; ks < 8; ks++) {
                    const int k0 = ks * 16;
                    const float* zr = &zc[(R1 + g) * ZSTR + k0 + 2 * tg];
                    float2 p0 = *(const float2*)zr;                      // row g,   k..k+1
                    float2 p2 = *(const float2*)(zr + 8);                // row g,   k+8..k+9
                    float2 p1 = *(const float2*)(zr + 8 * ZSTR);         // row g+8, k..k+1
                    float2 p3 = *(const float2*)(zr + 8 * ZSTR + 8);     // row g+8, k+8..k+9
                    s0 += p0.x + p0.y + p2.x + p2.y;
                    q0 += p0.x * p0.x + p0.y * p0.y + p2.x * p2.x + p2.y * p2.y;
                    s1 += p1.x + p1.y + p3.x + p3.y;
                    q1 += p1.x * p1.x + p1.y * p1.y + p3.x * p3.x + p3.y * p3.y;
                    u32 afr[4];
                    afr[0] = packh2(p0.x, p0.y);
                    afr[1] = packh2(p1.x, p1.y);
                    afr[2] = packh2(p2.x, p2.y);
                    afr[3] = packh2(p3.x, p3.y);
                    const u32* wbase = &smu[W1H_F + (8 * ks + tg) * W1STR + g];
                    #pragma unroll
                    for (int nt = 0; nt < 8; nt++) {
                        u32 b0 = wbase[8 * nt];
                        u32 b1 = wbase[8 * nt + 4 * W1STR];
                        mma16(acc[nt], afr, b0, b1);
                    }
                }

                // LN1 finalize (reduce over tg lanes)
                float m1a, r1a, m1b, r1b;
                {
                    float sa = s0, qa = q0, sb = s1, qb = q1;
                    sa += __shfl_xor_sync(0xffffffffu, sa, 1);
                    qa += __shfl_xor_sync(0xffffffffu, qa, 1);
                    sb += __shfl_xor_sync(0xffffffffu, sb, 1);
                    qb += __shfl_xor_sync(0xffffffffu, qb, 1);
                    sa += __shfl_xor_sync(0xffffffffu, sa, 2);
                    qa += __shfl_xor_sync(0xffffffffu, qa, 2);
                    sb += __shfl_xor_sync(0xffffffffu, sb, 2);
                    qb += __shfl_xor_sync(0xffffffffu, qb, 2);
                    m1a = sa * (1.f / TZ);
                    float va = fmaxf(qa * (1.f / TZ) - m1a * m1a, 0.f);
                    r1a = rsqrtf(va + EPSF);
                    m1b = sb * (1.f / TZ);
                    float vb_ = fmaxf(qb * (1.f / TZ) - m1b * m1b, 0.f);
                    r1b = rsqrtf(vb_ + EPSF);
                }

                // ---- epilogue 1: LN1-fold + bin column + LN2 stats (warp-local) ----
                float s2a = 0.f, q2a = 0.f, s2b = 0.f, q2b = 0.f;
                #pragma unroll
                for (int nt = 0; nt < 8; nt++) {
                    const int col = 8 * nt + 2 * tg;
                    float2 Sv = *(const float2*)&smf[S_F + col];
                    float2 Tv = *(const float2*)&smf[T_F + col];
                    float2 W0 = *(const float2*)&smf[WAS_F + bin0 * TD + col];
                    float2 W1v = *(const float2*)&smf[WAS_F + bin1 * TD + col];
                    float v0 = r1a * (acc[nt][0] - m1a * Sv.x) + Tv.x + mk0 * W0.x;
                    float v1 = r1a * (acc[nt][1] - m1a * Sv.y) + Tv.y + mk0 * W0.y;
                    float v2 = r1b * (acc[nt][2] - m1b * Sv.x) + Tv.x + mk1 * W1v.x;
                    float v3 = r1b * (acc[nt][3] - m1b * Sv.y) + Tv.y + mk1 * W1v.y;
                    acc[nt][0] = v0; acc[nt][1] = v1; acc[nt][2] = v2; acc[nt][3] = v3;
                    s2a += v0 + v1;  q2a += v0 * v0 + v1 * v1;
                    s2b += v2 + v3;  q2b += v2 * v2 + v3 * v3;
                }
                s2a += __shfl_xor_sync(0xffffffffu, s2a, 1);
                q2a += __shfl_xor_sync(0xffffffffu, q2a, 1);
                s2b += __shfl_xor_sync(0xffffffffu, s2b, 1);
                q2b += __shfl_xor_sync(0xffffffffu, q2b, 1);
                s2a += __shfl_xor_sync(0xffffffffu, s2a, 2);
                q2a += __shfl_xor_sync(0xffffffffu, q2a, 2);
                s2b += __shfl_xor_sync(0xffffffffu, s2b, 2);
                q2b += __shfl_xor_sync(0xffffffffu, q2b, 2);
                float m2a = s2a * (1.f / TD);
                float vva = fmaxf(q2a * (1.f / TD) - m2a * m2a, 0.f);
                float sca = 2.f * rsqrtf(4.f * vva + EPSF);    // exact v+v doubling
                float m2b = s2b * (1.f / TD);
                float vvb = fmaxf(q2b * (1.f / TD) - m2b * m2b, 0.f);
                float scb = 2.f * rsqrtf(4.f * vvb + EPSF);

                // ---- normalize + relu -> vn (half2 packed along d) ----
                #pragma unroll
                for (int nt = 0; nt < 8; nt++) {
                    const int col = 8 * nt + 2 * tg;
                    float2 gv = *(const float2*)&smf[VG_F + col];
                    float2 bv = *(const float2*)&smf[VB_F + col];
                    float a0 = fmaxf(fmaf((acc[nt][0] - m2a) * sca, gv.x, bv.x), 0.f);
                    float a1 = fmaxf(fmaf((acc[nt][1] - m2a) * sca, gv.y, bv.y), 0.f);
                    float b0 = fmaxf(fmaf((acc[nt][2] - m2b) * scb, gv.x, bv.x), 0.f);
                    float b1 = fmaxf(fmaf((acc[nt][3] - m2b) * scb, gv.y, bv.y), 0.f);
                    const int kp = 4 * nt + tg;                  // d-pair index
                    vncur[(R1 + g) * VNSTR + kp]     = packh2(a0, a1);
                    vncur[(R1 + g + 8) * VNSTR + kp] = packh2(b0, b1);
                }
            }
        } else {
            // ---- prefetch next z first (max overlap), then GEMM2 ----
            const int tile_next = tile + NBLOCKS;
            if (tile_next < NTILES) {
                const float* src = z + (size_t)tile_next * TM * TZ;
                #pragma unroll
                for (int i = 0; i < 16; i++) {
                    int e = i * 256 + t2;
                    cpa16(&znxt[(e >> 5) * ZSTR + (e & 31) * 4], src + e * 4);
                }
                cpa_commit();
            }

            // ---- GEMM2 fp16 (warp tile 16x128, 4 k16-steps) on vn(tile-NBLOCKS) ----
            if (it > 0) {
                const int base_p = (tile - NBLOCKS) * TM;
                float acc2[16][4];
                #pragma unroll
                for (int b = 0; b < 16; b++)
                    #pragma unroll
                    for (int cI = 0; cI < 4; cI++) acc2[b][cI] = 0.f;

                #pragma unroll
                for (int ks = 0; ks < 4; ks++) {
                    const u32* vr = &vnprev[(R1 + g) * VNSTR + 8 * ks + tg];
                    u32 afr[4];
                    afr[0] = vr[0];                    // row g,   d-pair kp
                    afr[1] = vr[8 * VNSTR];            // row g+8, kp
                    afr[2] = vr[4];                    // row g,   kp+4
                    afr[3] = vr[8 * VNSTR + 4];        // row g+8, kp+4
                    const u32* wbase = &smu[W2H_F + (8 * ks + tg) * W2STR + g];
                    #pragma unroll
                    for (int nt = 0; nt < 16; nt++) {
                        u32 b0 = wbase[8 * nt];
                        u32 b1 = wbase[8 * nt + 4 * W2STR];
                        mma16(acc2[nt], afr, b0, b1);
                    }
                }
                {
                    const int ra = base_p + R1 + g;
                    #pragma unroll
                    for (int nt = 0; nt < 16; nt++) {
                        const int col = 8 * nt + 2 * tg;
                        *(float2*)&out[(size_t)ra * TZ + col] =
                            make_float2(acc2[nt][0], acc2[nt][1]);
                        *(float2*)&out[(size_t)(ra + 8) * TZ + col] =
                            make_float2(acc2[nt][2], acc2[nt][3]);
                    }
                }
            }
        }
    }
}

// ---------------- launch ----------------
extern "C" void kernel_launch(void* const* d_in, const int* in_sizes, int n_in,
                              void* d_out, int out_size) {
    const float* z   = (const float*)d_in[0];   // (1,1024,1024,128)
    const float* cc  = (const float*)d_in[1];   // (1,1024,3)
    const float* tdm = (const float*)d_in[2];   // (1,1024,1024)
    // d_in[3] = pair_mask (unused by reference)
    const float* Wz  = (const float*)d_in[4];   // (64,128)
    const float* Wa  = (const float*)d_in[5];   // (64,38)
    const float* Wu  = (const float*)d_in[6];   // (128,64)
    const float* zg  = (const float*)d_in[7];   // (128)
    const float* zb  = (const float*)d_in[8];   // (128)
    const float* vg  = (const float*)d_in[9];   // (64)
    const float* vb  = (const float*)d_in[10];  // (64)
    float* out = (float*)d_out;

    size_t smem_bytes = (size_t)SMEM_FLOATS * sizeof(float);
    cudaFuncSetAttribute(td_kernel, cudaFuncAttributeMaxDynamicSharedMemorySize, (int)smem_bytes);
    td_kernel<<<NBLOCKS, THREADS, smem_bytes>>>(z, cc, tdm, Wz, Wa, Wu, zg, zb, vg, vb, out);
}